// round 9
// baseline (speedup 1.0000x reference)
#include <cuda_runtime.h>
#include <cuda_fp16.h>
#include <cstdint>

#define NN      50000
#define EE      800000
#define EP      850000      // EE + NN self loops
#define NG      50
#define DH      128
#define CAP     64          // bucket capacity; P(Poisson(16)+1 > 64) ~ 1e-18

// ---------------- scratch (device globals) ----------------------------------
__device__ __half2 g_feath[NN * 64];   // h in fp16 (gather-only consumer)
__device__ float g_out [NN * DH];
__device__ float g_als [NN * 2];
__device__ float g_ald [NN * 2];
__device__ int   g_bcnt [NN];          // bucket counts; reset by k_agg<1>
__device__ int   g_slots[NN * CAP];    // src indices per dst bucket
__device__ float g_pool[NG * DH];      // zeroed by k_build
__device__ float g_cnt [NG];
__device__ int   g_done;               // last-block counter; reset by last block

__device__ __forceinline__ void redAddV4(float* p, float a, float b, float c, float d) {
    asm volatile("red.global.add.v4.f32 [%0], {%1,%2,%3,%4};"
                 :: "l"(p), "f"(a), "f"(b), "f"(c), "f"(d) : "memory");
}

// packed f32x2 helpers --------------------------------------------------------
__device__ __forceinline__ unsigned long long pack2(float lo, float hi) {
    unsigned long long r;
    asm("mov.b64 %0, {%1,%2};" : "=l"(r) : "f"(lo), "f"(hi));
    return r;
}
__device__ __forceinline__ void fma2(unsigned long long& d,
                                     unsigned long long a, unsigned long long b) {
    asm("fma.rn.f32x2 %0, %1, %2, %0;" : "+l"(d) : "l"(a), "l"(b));
}
__device__ __forceinline__ void unpack2(float& lo, float& hi, unsigned long long v) {
    asm("mov.b64 {%0,%1}, %2;" : "=f"(lo), "=f"(hi) : "l"(v));
}

// ---------------- bucket build: whole "CSR" in one kernel -------------------
__global__ void k_build(const int* __restrict__ ei) {
    int e = blockIdx.x * blockDim.x + threadIdx.x;
    if (e < NG * DH) g_pool[e] = 0.0f;        // pool zeroing piggybacked
    if (e < NG)      g_cnt[e]  = 0.0f;
    if (e >= EP) return;
    int s, d;
    if (e < EE) { s = ei[e]; d = ei[EE + e]; }
    else        { s = d = e - EE; }
    int pos = atomicAdd(&g_bcnt[d], 1);
    if (pos < CAP) g_slots[d * CAP + pos] = s;
}

// ---------------- SGEMM (f32x2 packed) + logits epilogue, fp16 feat store ---
__global__ void k_gemm(const float* __restrict__ Aext, const float* __restrict__ W,
                       const float* __restrict__ a_s, const float* __restrict__ a_d) {
    const float* A = Aext ? Aext : g_out;
    __shared__ float xs[16][68];
    __shared__ float ws[16][128];
    int bm  = blockIdx.x * 64;
    int tid = threadIdx.x;
    int cg  = tid & 31;
    int rg  = tid >> 5;

    unsigned long long acc2[4][4];
#pragma unroll
    for (int r2 = 0; r2 < 4; r2++)
#pragma unroll
        for (int c = 0; c < 4; c++) acc2[r2][c] = 0ull;

    for (int k0 = 0; k0 < 128; k0 += 16) {
        {
            int r   = tid >> 2;
            int kk4 = (tid & 3) * 4;
            int row = bm + r;
            float4 v = make_float4(0.f, 0.f, 0.f, 0.f);
            if (row < NN) v = *(const float4*)(A + (size_t)row * 128 + k0 + kk4);
            xs[kk4 + 0][r] = v.x; xs[kk4 + 1][r] = v.y;
            xs[kk4 + 2][r] = v.z; xs[kk4 + 3][r] = v.w;
        }
        {
            const float4* Wp = (const float4*)(W + (size_t)k0 * 128);
            float4* wsp = (float4*)&ws[0][0];
            wsp[tid * 2 + 0] = Wp[tid * 2 + 0];
            wsp[tid * 2 + 1] = Wp[tid * 2 + 1];
        }
        __syncthreads();
#pragma unroll
        for (int kk = 0; kk < 16; kk++) {
            float4 bq = *(float4*)&ws[kk][cg * 4];
            unsigned long long bb[4];
            bb[0] = pack2(bq.x, bq.x); bb[1] = pack2(bq.y, bq.y);
            bb[2] = pack2(bq.z, bq.z); bb[3] = pack2(bq.w, bq.w);
            const unsigned long long* ap =
                (const unsigned long long*)&xs[kk][rg * 8];
#pragma unroll
            for (int r2 = 0; r2 < 4; r2++) {
                unsigned long long aa = ap[r2];
                fma2(acc2[r2][0], aa, bb[0]);
                fma2(acc2[r2][1], aa, bb[1]);
                fma2(acc2[r2][2], aa, bb[2]);
                fma2(acc2[r2][3], aa, bb[3]);
            }
        }
        __syncthreads();
    }

    float acc[8][4];
#pragma unroll
    for (int r2 = 0; r2 < 4; r2++)
#pragma unroll
        for (int c = 0; c < 4; c++)
            unpack2(acc[2 * r2][c], acc[2 * r2 + 1][c], acc2[r2][c]);

    const float4 asv = *(const float4*)(a_s + cg * 4);
    const float4 adv = *(const float4*)(a_d + cg * 4);
#pragma unroll
    for (int r = 0; r < 8; r++) {
        int row = bm + rg * 8 + r;
        float ps = acc[r][0]*asv.x + acc[r][1]*asv.y + acc[r][2]*asv.z + acc[r][3]*asv.w;
        float pd = acc[r][0]*adv.x + acc[r][1]*adv.y + acc[r][2]*adv.z + acc[r][3]*adv.w;
#pragma unroll
        for (int off = 8; off > 0; off >>= 1) {
            ps += __shfl_down_sync(0xffffffffu, ps, off, 16);
            pd += __shfl_down_sync(0xffffffffu, pd, off, 16);
        }
        if (row < NN) {
            if ((cg & 15) == 0) {
                int head = cg >> 4;
                g_als[row * 2 + head] = ps;
                g_ald[row * 2 + head] = pd;
            }
            __half2 p0 = __float22half2_rn(make_float2(acc[r][0], acc[r][1]));
            __half2 p1 = __float22half2_rn(make_float2(acc[r][2], acc[r][3]));
            uint2 u = make_uint2(*(unsigned*)&p0, *(unsigned*)&p1);
            *(uint2*)(g_feath + (size_t)row * 64 + cg * 2) = u;
        }
    }
}

// ------- single-pass softmax-weighted aggregation (warp per dst) ------------
// MODE 0: relu(agg+bias) -> g_out.   MODE 1: accumulate pool; last block: head.
template <int MODE>
__global__ void k_agg(const float* __restrict__ bias, const int* __restrict__ batch,
                      const float* __restrict__ Wh, const float* __restrict__ bh,
                      float* __restrict__ out) {
    int gw   = (blockIdx.x * blockDim.x + threadIdx.x) >> 5;   // == dst node
    int lane = threadIdx.x & 31;
    const int d    = gw;                                        // grid exact: gw < NN
    const int head = lane >> 4;

    const int n = min(g_bcnt[d], CAP);
    const int* __restrict__ slots = g_slots + d * CAP;
    if (MODE == 1 && lane == 0) g_bcnt[d] = 0;   // last reader resets for next call

    const float2 aldv = *(const float2*)(g_ald + d * 2);
    const float ald_h = head ? aldv.y : aldv.x;

    float4 acc = make_float4(0.f, 0.f, 0.f, 0.f);
    float ssum = 0.f;
    int i = 0;
    for (; i + 4 <= n; i += 4) {
        int sA = slots[i],     sB = slots[i + 1];
        int sC = slots[i + 2], sD = slots[i + 3];
        float eA = g_als[sA * 2 + head], eB = g_als[sB * 2 + head];
        float eC = g_als[sC * 2 + head], eD = g_als[sD * 2 + head];
        uint2 uA = *(const uint2*)(g_feath + (size_t)sA * 64 + lane * 2);
        uint2 uB = *(const uint2*)(g_feath + (size_t)sB * 64 + lane * 2);
        uint2 uC = *(const uint2*)(g_feath + (size_t)sC * 64 + lane * 2);
        uint2 uD = *(const uint2*)(g_feath + (size_t)sD * 64 + lane * 2);
        eA += ald_h; eA = (eA > 0.f) ? eA : 0.2f * eA;
        eB += ald_h; eB = (eB > 0.f) ? eB : 0.2f * eB;
        eC += ald_h; eC = (eC > 0.f) ? eC : 0.2f * eC;
        eD += ald_h; eD = (eD > 0.f) ? eD : 0.2f * eD;
        float wA = __expf(eA), wB = __expf(eB);
        float wC = __expf(eC), wD = __expf(eD);
        ssum += (wA + wB) + (wC + wD);
        float2 a0 = __half22float2(*(__half2*)&uA.x);
        float2 a1 = __half22float2(*(__half2*)&uA.y);
        float2 b0 = __half22float2(*(__half2*)&uB.x);
        float2 b1 = __half22float2(*(__half2*)&uB.y);
        float2 c0 = __half22float2(*(__half2*)&uC.x);
        float2 c1 = __half22float2(*(__half2*)&uC.y);
        float2 d0 = __half22float2(*(__half2*)&uD.x);
        float2 d1 = __half22float2(*(__half2*)&uD.y);
        acc.x = fmaf(wA, a0.x, acc.x); acc.y = fmaf(wA, a0.y, acc.y);
        acc.z = fmaf(wA, a1.x, acc.z); acc.w = fmaf(wA, a1.y, acc.w);
        acc.x = fmaf(wB, b0.x, acc.x); acc.y = fmaf(wB, b0.y, acc.y);
        acc.z = fmaf(wB, b1.x, acc.z); acc.w = fmaf(wB, b1.y, acc.w);
        acc.x = fmaf(wC, c0.x, acc.x); acc.y = fmaf(wC, c0.y, acc.y);
        acc.z = fmaf(wC, c1.x, acc.z); acc.w = fmaf(wC, c1.y, acc.w);
        acc.x = fmaf(wD, d0.x, acc.x); acc.y = fmaf(wD, d0.y, acc.y);
        acc.z = fmaf(wD, d1.x, acc.z); acc.w = fmaf(wD, d1.y, acc.w);
    }
    for (; i < n; i++) {
        int s = slots[i];
        float e = g_als[s * 2 + head] + ald_h;
        e = (e > 0.f) ? e : 0.2f * e;
        float w = __expf(e);
        ssum += w;
        uint2 u = *(const uint2*)(g_feath + (size_t)s * 64 + lane * 2);
        float2 a0 = __half22float2(*(__half2*)&u.x);
        float2 a1 = __half22float2(*(__half2*)&u.y);
        acc.x = fmaf(w, a0.x, acc.x); acc.y = fmaf(w, a0.y, acc.y);
        acc.z = fmaf(w, a1.x, acc.z); acc.w = fmaf(w, a1.y, acc.w);
    }

    const float inv = 1.0f / (ssum + 1e-16f);
    const float4 bv = *(const float4*)(bias + lane * 4);
    acc.x = fmaxf(fmaf(acc.x, inv, bv.x), 0.f);
    acc.y = fmaxf(fmaf(acc.y, inv, bv.y), 0.f);
    acc.z = fmaxf(fmaf(acc.z, inv, bv.z), 0.f);
    acc.w = fmaxf(fmaf(acc.w, inv, bv.w), 0.f);

    if (MODE == 0) {
        *(float4*)(g_out + (size_t)d * 128 + lane * 4) = acc;
    } else {
        int g = batch[d];
        redAddV4(g_pool + g * 128 + lane * 4, acc.x, acc.y, acc.z, acc.w);
        if (lane == 0) atomicAdd(&g_cnt[g], 1.0f);

        // ---- fused head: last block reduces pool @ Wh + bh -----------------
        __shared__ int isLast;
        __threadfence();
        __syncthreads();
        if (threadIdx.x == 0)
            isLast = (atomicAdd(&g_done, 1) == (int)gridDim.x - 1);
        __syncthreads();
        if (isLast) {
            __threadfence();
            int w = threadIdx.x >> 5;
            const float4 wv = *(const float4*)(Wh + lane * 4);
            for (int g2 = w; g2 < NG; g2 += 8) {
                float denom = fmaxf(__ldcg(&g_cnt[g2]), 1.0f);
                float4 p = __ldcg((const float4*)(g_pool + g2 * 128 + lane * 4));
                float v = p.x * wv.x + p.y * wv.y + p.z * wv.z + p.w * wv.w;
#pragma unroll
                for (int off = 16; off > 0; off >>= 1)
                    v += __shfl_down_sync(0xffffffffu, v, off);
                if (lane == 0) out[g2] = v / denom + bh[0];
            }
            __syncthreads();
            if (threadIdx.x == 0) g_done = 0;    // reset for next call
        }
    }
}

// ---------------- launch ----------------------------------------------------
extern "C" void kernel_launch(void* const* d_in, const int* in_sizes, int n_in,
                              void* d_out, int out_size) {
    const float* x     = (const float*)d_in[0];
    const int*   ei    = (const int*)d_in[1];
    const int*   batch = (const int*)d_in[2];
    const float* W1    = (const float*)d_in[3];
    const float* as1   = (const float*)d_in[4];
    const float* ad1   = (const float*)d_in[5];
    const float* b1    = (const float*)d_in[6];
    const float* W2    = (const float*)d_in[7];
    const float* as2   = (const float*)d_in[8];
    const float* ad2   = (const float*)d_in[9];
    const float* b2    = (const float*)d_in[10];
    const float* Wh    = (const float*)d_in[11];
    const float* bh    = (const float*)d_in[12];
    float* out = (float*)d_out;

    // one-time host-side infrastructure (no device memory, identical work/call)
    static cudaStream_t s2 = nullptr;
    static cudaEvent_t  evFork = nullptr, evGemm = nullptr;
    if (!s2) {
        cudaStreamCreateWithFlags(&s2, cudaStreamNonBlocking);
        cudaEventCreateWithFlags(&evFork, cudaEventDisableTiming);
        cudaEventCreateWithFlags(&evGemm, cudaEventDisableTiming);
    }

    const int TB = 256;
    int grid_edges = (EP + TB - 1) / TB;     // 3321
    int grid_gemm  = (NN + 63) / 64;         // 782
    int grid_agg   = NN * 32 / TB;           // 6250 exact

    // fork: layer-1 GEMM runs concurrently with the bucket build
    cudaEventRecord(evFork, 0);
    cudaStreamWaitEvent(s2, evFork, 0);
    k_gemm<<<grid_gemm, TB, 0, s2>>>(x, W1, as1, ad1);
    cudaEventRecord(evGemm, s2);

    // bucket build on main stream (g_bcnt arrives zeroed: BSS / k_agg<1>)
    k_build<<<grid_edges, TB>>>(ei);

    // join, then layer-1 aggregation
    cudaStreamWaitEvent(0, evGemm, 0);
    k_agg<0><<<grid_agg, TB>>>(b1, batch, Wh, bh, out);

    // layer 2 + fused head
    k_gemm<<<grid_gemm, TB>>>(nullptr, W2, as2, ad2);
    k_agg<1><<<grid_agg, TB>>>(b2, batch, Wh, bh, out);
}

// round 16
// speedup vs baseline: 1.1476x; 1.1476x over previous
#include <cuda_runtime.h>
#include <cuda_fp16.h>
#include <cstdint>

#define NN      50000
#define EE      800000
#define EP      850000      // EE + NN self loops
#define NG      50
#define DH      128
#define CAP     64          // bucket capacity; P(Poisson(17) > 64) ~ 1e-18

// ---------------- scratch (device globals) ----------------------------------
__device__ __half  g_ah  [(NN + 128) * DH]; // fp16 A operand (pad: tile overreads)
__device__ __half2 g_feath[NN * 64];        // h in fp16 (gather consumer)
__device__ unsigned g_w1p[8192];            // W1 hi, mma-fragment order
__device__ unsigned g_w1q[8192];            // W1 lo (residual)
__device__ unsigned g_w2p[8192];            // W2 hi
__device__ unsigned g_w2q[8192];            // W2 lo
__device__ float g_wa  [8 * DH];            // W@a vectors: (layer*4+sd*2+head)*128+k
__device__ float g_als [NN * 2];            // layer-1 logits
__device__ float g_ald [NN * 2];
__device__ float g_als2[NN * 2];            // layer-2 logits (separate buffers)
__device__ float g_ald2[NN * 2];
__device__ int   g_bcnt [NN];               // bucket counts; reset by k_agg<1>
__device__ int   g_slots[NN * CAP];         // src indices per dst bucket
__device__ float g_pool[NG * DH];           // zeroed by k_build
__device__ float g_cnt [NG];

__device__ __forceinline__ void redAddV4(float* p, float a, float b, float c, float d) {
    asm volatile("red.global.add.v4.f32 [%0], {%1,%2,%3,%4};"
                 :: "l"(p), "f"(a), "f"(b), "f"(c), "f"(d) : "memory");
}

// ---------------- converts ---------------------------------------------------
// W -> fragment-linear order, SPLIT precision: hi = fp16(w), lo = fp16(w - hi).
// u32 index i = ((kc*16 + nf)*32 + lane)*2 + reg holds halves (W[k][n], W[k+1][n])
// with n = nf*8 + lane/4, k = kc*16 + (lane%4)*2 + reg*8.
__global__ void k_cw(const float* __restrict__ W1, const float* __restrict__ W2) {
    int i = blockIdx.x * blockDim.x + threadIdx.x;
    if (i >= 8192) return;
    int reg = i & 1, lane = (i >> 1) & 31, nf = (i >> 6) & 15, kc = i >> 10;
    int n = nf * 8 + (lane >> 2);
    int k = kc * 16 + (lane & 3) * 2 + reg * 8;
    float a0 = W1[k * 128 + n], a1 = W1[(k + 1) * 128 + n];
    float b0 = W2[k * 128 + n], b1 = W2[(k + 1) * 128 + n];
    __half h_a0 = __float2half_rn(a0), h_a1 = __float2half_rn(a1);
    __half h_b0 = __float2half_rn(b0), h_b1 = __float2half_rn(b1);
    __half2 p1h = __halves2half2(h_a0, h_a1);
    __half2 p2h = __halves2half2(h_b0, h_b1);
    __half2 p1l = __floats2half2_rn(a0 - __half2float(h_a0), a1 - __half2float(h_a1));
    __half2 p2l = __floats2half2_rn(b0 - __half2float(h_b0), b1 - __half2float(h_b1));
    g_w1p[i] = *(unsigned*)&p1h;  g_w1q[i] = *(unsigned*)&p1l;
    g_w2p[i] = *(unsigned*)&p2h;  g_w2q[i] = *(unsigned*)&p2l;
}

// fp32 fused attention vectors: g_wa[(layer*4+sd*2+head)*128+k]
//   = sum_c W[k][head*64+c] * a[head*64+c]
__global__ void k_wa(const float* __restrict__ W1, const float* __restrict__ as1,
                     const float* __restrict__ ad1, const float* __restrict__ W2,
                     const float* __restrict__ as2, const float* __restrict__ ad2) {
    int i = blockIdx.x * blockDim.x + threadIdx.x;   // 1024
    if (i >= 8 * DH) return;
    int k = i & 127, v = i >> 7;
    int layer = v >> 2, sd = (v >> 1) & 1, head = v & 1;
    const float* W = layer ? W2 : W1;
    const float* a = layer ? (sd ? ad2 : as2) : (sd ? ad1 : as1);
    float s = 0.f;
    const float* wr = W + k * 128 + head * 64;
    const float* ar = a + head * 64;
#pragma unroll 16
    for (int c = 0; c < 64; c++) s = fmaf(wr[c], ar[c], s);
    g_wa[i] = s;
}

// x -> fp16 A operand + fp32 layer-1 logits (warp per node)
__global__ void k_x2h(const float* __restrict__ x) {
    int gt   = blockIdx.x * blockDim.x + threadIdx.x;
    int node = gt >> 5, lane = gt & 31;
    if (node >= NN) return;
    float4 v = *(const float4*)(x + (size_t)node * 128 + lane * 4);
    __half2 p0 = __float22half2_rn(make_float2(v.x, v.y));
    __half2 p1 = __float22half2_rn(make_float2(v.z, v.w));
    *(uint2*)(g_ah + (size_t)node * 128 + lane * 4) =
        make_uint2(*(unsigned*)&p0, *(unsigned*)&p1);
    float4 s0 = *(const float4*)(g_wa + 0 * 128 + lane * 4);
    float4 s1 = *(const float4*)(g_wa + 1 * 128 + lane * 4);
    float4 d0 = *(const float4*)(g_wa + 2 * 128 + lane * 4);
    float4 d1 = *(const float4*)(g_wa + 3 * 128 + lane * 4);
    float ps0 = v.x*s0.x + v.y*s0.y + v.z*s0.z + v.w*s0.w;
    float ps1 = v.x*s1.x + v.y*s1.y + v.z*s1.z + v.w*s1.w;
    float pd0 = v.x*d0.x + v.y*d0.y + v.z*d0.z + v.w*d0.w;
    float pd1 = v.x*d1.x + v.y*d1.y + v.z*d1.z + v.w*d1.w;
#pragma unroll
    for (int off = 16; off > 0; off >>= 1) {
        ps0 += __shfl_xor_sync(0xffffffffu, ps0, off);
        ps1 += __shfl_xor_sync(0xffffffffu, ps1, off);
        pd0 += __shfl_xor_sync(0xffffffffu, pd0, off);
        pd1 += __shfl_xor_sync(0xffffffffu, pd1, off);
    }
    if (lane == 0) {
        g_als[node * 2 + 0] = ps0; g_als[node * 2 + 1] = ps1;
        g_ald[node * 2 + 0] = pd0; g_ald[node * 2 + 1] = pd1;
    }
}

// ---------------- bucket build: whole graph index in one kernel -------------
__global__ void k_build(const int* __restrict__ ei) {
    int e = blockIdx.x * blockDim.x + threadIdx.x;
    if (e < NG * DH) g_pool[e] = 0.0f;
    if (e < NG)      g_cnt[e]  = 0.0f;
    if (e >= EP) return;
    int s, d;
    if (e < EE) { s = ei[e]; d = ei[EE + e]; }
    else        { s = d = e - EE; }
    int pos = atomicAdd(&g_bcnt[d], 1);
    if (pos < CAP) g_slots[d * CAP + pos] = s;
}

// ------- tensor-core GEMM: mma.m16n8k16, split-precision W, no smem ---------
// c += A@W_hi + A@W_lo  (fp32 accum). Epilogue: fp16 feat store.
template <int LAYER>
__global__ void k_gemm_t() {
    const uint2* __restrict__ bh = (const uint2*)(LAYER ? g_w2p : g_w1p);
    const uint2* __restrict__ bl = (const uint2*)(LAYER ? g_w2q : g_w1q);
    const int w    = threadIdx.x >> 5;
    const int lane = threadIdx.x & 31;
    const int q    = lane & 3;
    const int g    = lane >> 2;
    const int r0   = blockIdx.x * 128 + w * 16 + g;     // rows r0 and r0+8
    const __half* A0 = g_ah + (size_t)r0 * 128 + q * 2;

    float c[16][4];
#pragma unroll
    for (int j = 0; j < 16; j++)
#pragma unroll
        for (int t = 0; t < 4; t++) c[j][t] = 0.0f;

#pragma unroll
    for (int kc = 0; kc < 8; kc++) {
        unsigned a0 = *(const unsigned*)(A0 + kc * 16);
        unsigned a1 = *(const unsigned*)(A0 + 8 * 128 + kc * 16);
        unsigned a2 = *(const unsigned*)(A0 + kc * 16 + 8);
        unsigned a3 = *(const unsigned*)(A0 + 8 * 128 + kc * 16 + 8);
#pragma unroll
        for (int nf = 0; nf < 16; nf++) {
            uint2 bbh = bh[(kc * 16 + nf) * 32 + lane];
            uint2 bbl = bl[(kc * 16 + nf) * 32 + lane];
            asm volatile(
                "mma.sync.aligned.m16n8k16.row.col.f32.f16.f16.f32 "
                "{%0,%1,%2,%3}, {%4,%5,%6,%7}, {%8,%9}, {%0,%1,%2,%3};\n"
                : "+f"(c[nf][0]), "+f"(c[nf][1]), "+f"(c[nf][2]), "+f"(c[nf][3])
                : "r"(a0), "r"(a1), "r"(a2), "r"(a3), "r"(bbh.x), "r"(bbh.y));
            asm volatile(
                "mma.sync.aligned.m16n8k16.row.col.f32.f16.f16.f32 "
                "{%0,%1,%2,%3}, {%4,%5,%6,%7}, {%8,%9}, {%0,%1,%2,%3};\n"
                : "+f"(c[nf][0]), "+f"(c[nf][1]), "+f"(c[nf][2]), "+f"(c[nf][3])
                : "r"(a0), "r"(a1), "r"(a2), "r"(a3), "r"(bbl.x), "r"(bbl.y));
        }
    }

    const bool ok0 = (r0 < NN), ok1 = (r0 + 8 < NN);
#pragma unroll
    for (int j = 0; j < 16; j++) {
        if (ok0) g_feath[(size_t)r0 * 64 + j * 4 + q] =
                     __floats2half2_rn(c[j][0], c[j][1]);
        if (ok1) g_feath[(size_t)(r0 + 8) * 64 + j * 4 + q] =
                     __floats2half2_rn(c[j][2], c[j][3]);
    }
}

// ------- single-pass softmax-weighted aggregation (warp per dst) ------------
// MODE 0: reads layer-1 logits; writes fp16 A + layer-2 logits to *2 buffers.
// MODE 1: reads *2 buffers; accumulates pool; resets g_bcnt.
template <int MODE>
__global__ void k_agg(const float* __restrict__ bias, const int* __restrict__ batch) {
    int gw   = (blockIdx.x * blockDim.x + threadIdx.x) >> 5;   // dst node, exact
    int lane = threadIdx.x & 31;
    const int d    = gw;
    const int head = lane >> 4;

    const float* __restrict__ als = MODE ? g_als2 : g_als;
    const float* __restrict__ ald = MODE ? g_ald2 : g_ald;

    const int n = min(g_bcnt[d], CAP);
    const int* __restrict__ slots = g_slots + d * CAP;
    if (MODE == 1 && lane == 0) g_bcnt[d] = 0;   // last reader resets for next call

    const float2 aldv = *(const float2*)(ald + d * 2);
    const float ald_h = head ? aldv.y : aldv.x;

    float4 acc = make_float4(0.f, 0.f, 0.f, 0.f);
    float ssum = 0.f;
    int i = 0;
    for (; i + 4 <= n; i += 4) {
        int sA = slots[i],     sB = slots[i + 1];
        int sC = slots[i + 2], sD = slots[i + 3];
        float eA = als[sA * 2 + head], eB = als[sB * 2 + head];
        float eC = als[sC * 2 + head], eD = als[sD * 2 + head];
        uint2 uA = *(const uint2*)(g_feath + (size_t)sA * 64 + lane * 2);
        uint2 uB = *(const uint2*)(g_feath + (size_t)sB * 64 + lane * 2);
        uint2 uC = *(const uint2*)(g_feath + (size_t)sC * 64 + lane * 2);
        uint2 uD = *(const uint2*)(g_feath + (size_t)sD * 64 + lane * 2);
        eA += ald_h; eA = (eA > 0.f) ? eA : 0.2f * eA;
        eB += ald_h; eB = (eB > 0.f) ? eB : 0.2f * eB;
        eC += ald_h; eC = (eC > 0.f) ? eC : 0.2f * eC;
        eD += ald_h; eD = (eD > 0.f) ? eD : 0.2f * eD;
        float wA = __expf(eA), wB = __expf(eB);
        float wC = __expf(eC), wD = __expf(eD);
        ssum += (wA + wB) + (wC + wD);
        float2 a0 = __half22float2(*(__half2*)&uA.x);
        float2 a1 = __half22float2(*(__half2*)&uA.y);
        float2 b0 = __half22float2(*(__half2*)&uB.x);
        float2 b1 = __half22float2(*(__half2*)&uB.y);
        float2 c0 = __half22float2(*(__half2*)&uC.x);
        float2 c1 = __half22float2(*(__half2*)&uC.y);
        float2 d0 = __half22float2(*(__half2*)&uD.x);
        float2 d1 = __half22float2(*(__half2*)&uD.y);
        acc.x = fmaf(wA, a0.x, acc.x); acc.y = fmaf(wA, a0.y, acc.y);
        acc.z = fmaf(wA, a1.x, acc.z); acc.w = fmaf(wA, a1.y, acc.w);
        acc.x = fmaf(wB, b0.x, acc.x); acc.y = fmaf(wB, b0.y, acc.y);
        acc.z = fmaf(wB, b1.x, acc.z); acc.w = fmaf(wB, b1.y, acc.w);
        acc.x = fmaf(wC, c0.x, acc.x); acc.y = fmaf(wC, c0.y, acc.y);
        acc.z = fmaf(wC, c1.x, acc.z); acc.w = fmaf(wC, c1.y, acc.w);
        acc.x = fmaf(wD, d0.x, acc.x); acc.y = fmaf(wD, d0.y, acc.y);
        acc.z = fmaf(wD, d1.x, acc.z); acc.w = fmaf(wD, d1.y, acc.w);
    }
    for (; i < n; i++) {
        int s = slots[i];
        float e = als[s * 2 + head] + ald_h;
        e = (e > 0.f) ? e : 0.2f * e;
        float w = __expf(e);
        ssum += w;
        uint2 u = *(const uint2*)(g_feath + (size_t)s * 64 + lane * 2);
        float2 a0 = __half22float2(*(__half2*)&u.x);
        float2 a1 = __half22float2(*(__half2*)&u.y);
        acc.x = fmaf(w, a0.x, acc.x); acc.y = fmaf(w, a0.y, acc.y);
        acc.z = fmaf(w, a1.x, acc.z); acc.w = fmaf(w, a1.y, acc.w);
    }

    const float inv = 1.0f / (ssum + 1e-16f);
    const float4 bv = *(const float4*)(bias + lane * 4);
    acc.x = fmaxf(fmaf(acc.x, inv, bv.x), 0.f);
    acc.y = fmaxf(fmaf(acc.y, inv, bv.y), 0.f);
    acc.z = fmaxf(fmaf(acc.z, inv, bv.z), 0.f);
    acc.w = fmaxf(fmaf(acc.w, inv, bv.w), 0.f);

    if (MODE == 0) {
        __half2 p0 = __float22half2_rn(make_float2(acc.x, acc.y));
        __half2 p1 = __float22half2_rn(make_float2(acc.z, acc.w));
        *(uint2*)(g_ah + (size_t)d * 128 + lane * 4) =
            make_uint2(*(unsigned*)&p0, *(unsigned*)&p1);
        // fp32 layer-2 logits from the fp32 accumulator -> separate buffers
        float4 s0 = *(const float4*)(g_wa + 4 * 128 + lane * 4);
        float4 s1 = *(const float4*)(g_wa + 5 * 128 + lane * 4);
        float4 d0 = *(const float4*)(g_wa + 6 * 128 + lane * 4);
        float4 d1 = *(const float4*)(g_wa + 7 * 128 + lane * 4);
        float ps0 = acc.x*s0.x + acc.y*s0.y + acc.z*s0.z + acc.w*s0.w;
        float ps1 = acc.x*s1.x + acc.y*s1.y + acc.z*s1.z + acc.w*s1.w;
        float pd0 = acc.x*d0.x + acc.y*d0.y + acc.z*d0.z + acc.w*d0.w;
        float pd1 = acc.x*d1.x + acc.y*d1.y + acc.z*d1.z + acc.w*d1.w;
#pragma unroll
        for (int off = 16; off > 0; off >>= 1) {
            ps0 += __shfl_xor_sync(0xffffffffu, ps0, off);
            ps1 += __shfl_xor_sync(0xffffffffu, ps1, off);
            pd0 += __shfl_xor_sync(0xffffffffu, pd0, off);
            pd1 += __shfl_xor_sync(0xffffffffu, pd1, off);
        }
        if (lane == 0) {
            g_als2[d * 2 + 0] = ps0; g_als2[d * 2 + 1] = ps1;
            g_ald2[d * 2 + 0] = pd0; g_ald2[d * 2 + 1] = pd1;
        }
    } else {
        int g = batch[d];
        redAddV4(g_pool + g * 128 + lane * 4, acc.x, acc.y, acc.z, acc.w);
        if (lane == 0) atomicAdd(&g_cnt[g], 1.0f);
    }
}

// ---------------- head ------------------------------------------------------
__global__ void k_head(const float* __restrict__ Wh, const float* __restrict__ bh,
                       float* __restrict__ out) {
    int g = blockIdx.x;
    int t = threadIdx.x;
    float denom = fmaxf(g_cnt[g], 1.0f);
    float v = (g_pool[g * 128 + t] / denom) * Wh[t];
    __shared__ float sred[4];
#pragma unroll
    for (int off = 16; off > 0; off >>= 1) v += __shfl_down_sync(0xffffffffu, v, off);
    if ((t & 31) == 0) sred[t >> 5] = v;
    __syncthreads();
    if (t == 0) out[g] = sred[0] + sred[1] + sred[2] + sred[3] + bh[0];
}

// ---------------- launch ----------------------------------------------------
extern "C" void kernel_launch(void* const* d_in, const int* in_sizes, int n_in,
                              void* d_out, int out_size) {
    const float* x     = (const float*)d_in[0];
    const int*   ei    = (const int*)d_in[1];
    const int*   batch = (const int*)d_in[2];
    const float* W1    = (const float*)d_in[3];
    const float* as1   = (const float*)d_in[4];
    const float* ad1   = (const float*)d_in[5];
    const float* b1    = (const float*)d_in[6];
    const float* W2    = (const float*)d_in[7];
    const float* as2   = (const float*)d_in[8];
    const float* ad2   = (const float*)d_in[9];
    const float* b2    = (const float*)d_in[10];
    const float* Wh    = (const float*)d_in[11];
    const float* bh    = (const float*)d_in[12];
    float* out = (float*)d_out;

    // one-time host-side infrastructure (no device memory, identical work/call)
    static cudaStream_t s2 = nullptr;
    static cudaEvent_t  evFork = nullptr, evGemm = nullptr;
    if (!s2) {
        cudaStreamCreateWithFlags(&s2, cudaStreamNonBlocking);
        cudaEventCreateWithFlags(&evFork, cudaEventDisableTiming);
        cudaEventCreateWithFlags(&evGemm, cudaEventDisableTiming);
    }

    const int TB = 256;
    int grid_edges = (EP + TB - 1) / TB;       // 3321
    int grid_gemm  = (NN + 127) / 128;         // 391
    int grid_agg   = NN * 32 / TB;             // 6250 exact

    // fork: converts + layer-1 GEMM run concurrently with the bucket build
    cudaEventRecord(evFork, 0);
    cudaStreamWaitEvent(s2, evFork, 0);
    k_cw<<<32, TB, 0, s2>>>(W1, W2);
    k_wa<<<4, TB, 0, s2>>>(W1, as1, ad1, W2, as2, ad2);
    k_x2h<<<NN * 32 / TB, TB, 0, s2>>>(x);
    k_gemm_t<0><<<grid_gemm, TB, 0, s2>>>();
    cudaEventRecord(evGemm, s2);

    // bucket build on main stream (g_bcnt arrives zeroed: BSS / k_agg<1>)
    k_build<<<grid_edges, TB>>>(ei);

    // join, then layer-1 aggregation (emits fp16 A + layer-2 logits to *2 bufs)
    cudaStreamWaitEvent(0, evGemm, 0);
    k_agg<0><<<grid_agg, TB>>>(b1, batch);

    // layer 2
    k_gemm_t<1><<<grid_gemm, TB>>>();
    k_agg<1><<<grid_agg, TB>>>(b2, batch);

    // head
    k_head<<<NG, 128>>>(Wh, bh, out);
}